// round 1
// baseline (speedup 1.0000x reference)
#include <cuda_runtime.h>
#include <cuda_bf16.h>
#include <cstdint>

#define NUM_CLASSES 100000
#define EMBED 512
#define BATCH_N 4096
#define LAMBDA_C 0.01f
#define ALPHA_C 0.1f

// Zero the scalar loss slot (d_out is poisoned before timing).
__global__ void zero_loss_kernel(float* loss) {
    if (threadIdx.x == 0 && blockIdx.x == 0) *loss = 0.0f;
}

// One CTA per sample. 128 threads, each handles one float4 (512 floats / row).
// delta = batch[i] - centers[y[i]]
// atomicAdd(new_centers[y[i]], ALPHA * delta)   (duplicates accumulate)
// loss += LAMBDA * sum(delta^2) / BATCH
__global__ __launch_bounds__(128)
void center_loss_kernel(const int* __restrict__ y,
                        const float* __restrict__ batch,
                        const float* __restrict__ centers,
                        float* __restrict__ new_centers,
                        float* __restrict__ loss) {
    const int i = blockIdx.x;           // sample index
    const int t = threadIdx.x;          // 0..127, one float4 each
    const int cls = y[i];

    const float4* brow = reinterpret_cast<const float4*>(batch + (size_t)i * EMBED);
    const float4* crow = reinterpret_cast<const float4*>(centers + (size_t)cls * EMBED);
    float* nrow = new_centers + (size_t)cls * EMBED;

    float4 b4 = brow[t];
    float4 c4 = crow[t];

    float dx = b4.x - c4.x;
    float dy = b4.y - c4.y;
    float dz = b4.z - c4.z;
    float dw = b4.w - c4.w;

    // scatter-add (no float4 atomic; 4 scalar REDs, addresses mostly unique rows)
    const int base = t * 4;
    atomicAdd(nrow + base + 0, ALPHA_C * dx);
    atomicAdd(nrow + base + 1, ALPHA_C * dy);
    atomicAdd(nrow + base + 2, ALPHA_C * dz);
    atomicAdd(nrow + base + 3, ALPHA_C * dw);

    float s = dx * dx + dy * dy + dz * dz + dw * dw;

    // warp reduce
    #pragma unroll
    for (int off = 16; off > 0; off >>= 1)
        s += __shfl_xor_sync(0xFFFFFFFFu, s, off);

    __shared__ float warp_sums[4];
    if ((t & 31) == 0) warp_sums[t >> 5] = s;
    __syncthreads();

    if (t == 0) {
        float tot = warp_sums[0] + warp_sums[1] + warp_sums[2] + warp_sums[3];
        atomicAdd(loss, tot * (LAMBDA_C / (float)BATCH_N));
    }
}

extern "C" void kernel_launch(void* const* d_in, const int* in_sizes, int n_in,
                              void* d_out, int out_size) {
    const int*   y       = (const int*)d_in[0];
    const float* batch   = (const float*)d_in[1];
    const float* centers = (const float*)d_in[2];

    float* out = (float*)d_out;

    // Output layout: assume (loss, new_centers) flattened -> loss at out[0].
    float* loss_ptr;
    float* new_centers;
    const size_t ncs = (size_t)NUM_CLASSES * EMBED;
    if (out_size == (int)(ncs + 1)) {
        loss_ptr = out;
        new_centers = out + 1;
    } else {
        // fallback: centers first, loss last
        new_centers = out;
        loss_ptr = out + ncs;
    }

    // 1) new_centers = centers  (bulk D2D copy, HBM-bound)
    cudaMemcpyAsync(new_centers, centers, ncs * sizeof(float),
                    cudaMemcpyDeviceToDevice, 0);

    // 2) zero loss slot
    zero_loss_kernel<<<1, 32>>>(loss_ptr);

    // 3) gather/scatter/loss
    center_loss_kernel<<<BATCH_N, 128>>>(y, batch, centers, new_centers, loss_ptr);
}

// round 2
// speedup vs baseline: 1.9626x; 1.9626x over previous
#include <cuda_runtime.h>
#include <cuda_bf16.h>
#include <cstdint>

#define NUM_CLASSES 100000
#define EMBED 512
#define BATCH_N 4096
#define LAMBDA_C 0.01f
#define ALPHA_C 0.1f

// Copy centers -> new_centers (dst misaligned by 4B, so aligned 128-bit loads
// + scalar stores). Also zeroes the loss slot (block 0 / thread 0).
__global__ __launch_bounds__(256)
void copy_centers_kernel(const float4* __restrict__ src,
                         float* __restrict__ dst,
                         float* __restrict__ loss,
                         long n4) {
    long i = (long)blockIdx.x * blockDim.x + threadIdx.x;
    if (i == 0) *loss = 0.0f;
    if (i < n4) {
        float4 v = __ldcs(src + i);
        float* d = dst + i * 4;
        __stcs(d + 0, v.x);
        __stcs(d + 1, v.y);
        __stcs(d + 2, v.z);
        __stcs(d + 3, v.w);
    }
}

// One CTA per sample. 128 threads, each handles one float4 (512 floats / row).
__global__ __launch_bounds__(128)
void center_loss_kernel(const int* __restrict__ y,
                        const float* __restrict__ batch,
                        const float* __restrict__ centers,
                        float* __restrict__ new_centers,
                        float* __restrict__ loss) {
    const int i = blockIdx.x;           // sample index
    const int t = threadIdx.x;          // 0..127, one float4 each
    const int cls = y[i];

    const float4* brow = reinterpret_cast<const float4*>(batch + (size_t)i * EMBED);
    const float4* crow = reinterpret_cast<const float4*>(centers + (size_t)cls * EMBED);
    float* nrow = new_centers + (size_t)cls * EMBED;

    float4 b4 = brow[t];
    float4 c4 = crow[t];

    float dx = b4.x - c4.x;
    float dy = b4.y - c4.y;
    float dz = b4.z - c4.z;
    float dw = b4.w - c4.w;

    const int base = t * 4;
    atomicAdd(nrow + base + 0, ALPHA_C * dx);
    atomicAdd(nrow + base + 1, ALPHA_C * dy);
    atomicAdd(nrow + base + 2, ALPHA_C * dz);
    atomicAdd(nrow + base + 3, ALPHA_C * dw);

    float s = dx * dx + dy * dy + dz * dz + dw * dw;

    #pragma unroll
    for (int off = 16; off > 0; off >>= 1)
        s += __shfl_xor_sync(0xFFFFFFFFu, s, off);

    __shared__ float warp_sums[4];
    if ((t & 31) == 0) warp_sums[t >> 5] = s;
    __syncthreads();

    if (t == 0) {
        float tot = warp_sums[0] + warp_sums[1] + warp_sums[2] + warp_sums[3];
        atomicAdd(loss, tot * (LAMBDA_C / (float)BATCH_N));
    }
}

extern "C" void kernel_launch(void* const* d_in, const int* in_sizes, int n_in,
                              void* d_out, int out_size) {
    const int*   y       = (const int*)d_in[0];
    const float* batch   = (const float*)d_in[1];
    const float* centers = (const float*)d_in[2];

    float* out = (float*)d_out;

    const size_t ncs = (size_t)NUM_CLASSES * EMBED;
    float* loss_ptr;
    float* new_centers;
    if (out_size == (int)(ncs + 1)) {
        loss_ptr = out;
        new_centers = out + 1;
    } else {
        new_centers = out;
        loss_ptr = out + ncs;
    }

    // 1) new_centers = centers (custom copy; also zeroes loss)
    const long n4 = (long)(ncs / 4);     // 12.8M float4s
    const int threads = 256;
    const long blocks = (n4 + threads - 1) / threads;
    copy_centers_kernel<<<(unsigned)blocks, threads>>>(
        reinterpret_cast<const float4*>(centers), new_centers, loss_ptr, n4);

    // 2) gather / scatter-add / loss
    center_loss_kernel<<<BATCH_N, 128>>>(y, batch, centers, new_centers, loss_ptr);
}

// round 3
// speedup vs baseline: 2.2045x; 1.1232x over previous
#include <cuda_runtime.h>
#include <cuda_bf16.h>
#include <cstdint>

#define NUM_CLASSES 100000
#define EMBED 512
#define BATCH_N 4096
#define LAMBDA_C 0.01f
#define ALPHA_C 0.1f

// Per-class linked lists of sample indices (scratch; rebuilt every call).
__device__ int g_head[NUM_CLASSES];
__device__ int g_next[BATCH_N];

// 1) reset heads + zero loss slot
__global__ __launch_bounds__(256)
void init_kernel(float* __restrict__ loss) {
    int i = blockIdx.x * blockDim.x + threadIdx.x;
    if (i < NUM_CLASSES) g_head[i] = -1;
    if (i == 0) *loss = 0.0f;
}

// 2) build per-class chains: duplicates accumulate via the chain
__global__ __launch_bounds__(256)
void build_kernel(const int* __restrict__ y) {
    int i = blockIdx.x * blockDim.x + threadIdx.x;
    if (i < BATCH_N) {
        int c = y[i];
        int old = atomicExch(&g_head[c], i);
        g_next[i] = old;
    }
}

// 3) fused copy + apply: one streaming pass over all centers.
//    256 threads = 2 class rows per block; 128 threads / row, one float4 each.
__global__ __launch_bounds__(256)
void fused_copy_apply_kernel(const float4* __restrict__ centers4,
                             const float4* __restrict__ batch4,
                             float* __restrict__ dst,
                             float* __restrict__ loss) {
    const int row = blockIdx.x * 2 + (threadIdx.x >> 7);
    const int t   = threadIdx.x & 127;          // float4 index within row

    float4 c4 = __ldcs(centers4 + (size_t)row * (EMBED / 4) + t);
    int h = g_head[row];                        // uniform per half-block
    float4 v = c4;

    if (h >= 0) {
        float ax = 0.f, ay = 0.f, az = 0.f, aw = 0.f, ls = 0.f;
        int s = h;
        while (s >= 0) {
            float4 b4 = batch4[(size_t)s * (EMBED / 4) + t];
            float dx = b4.x - c4.x;
            float dy = b4.y - c4.y;
            float dz = b4.z - c4.z;
            float dw = b4.w - c4.w;
            ax += dx; ay += dy; az += dz; aw += dw;
            ls += dx * dx + dy * dy + dz * dz + dw * dw;
            s = g_next[s];
        }
        v.x += ALPHA_C * ax;
        v.y += ALPHA_C * ay;
        v.z += ALPHA_C * az;
        v.w += ALPHA_C * aw;

        // warp-level loss reduce (chain membership is uniform per 128-thread row,
        // hence uniform per warp)
        #pragma unroll
        for (int off = 16; off > 0; off >>= 1)
            ls += __shfl_xor_sync(0xFFFFFFFFu, ls, off);
        if ((t & 31) == 0)
            atomicAdd(loss, ls * (LAMBDA_C / (float)BATCH_N));
    }

    // dst row is misaligned by 4B (out+1) -> scalar stores
    float* d = dst + (size_t)row * EMBED + t * 4;
    __stcs(d + 0, v.x);
    __stcs(d + 1, v.y);
    __stcs(d + 2, v.z);
    __stcs(d + 3, v.w);
}

extern "C" void kernel_launch(void* const* d_in, const int* in_sizes, int n_in,
                              void* d_out, int out_size) {
    const int*   y       = (const int*)d_in[0];
    const float* batch   = (const float*)d_in[1];
    const float* centers = (const float*)d_in[2];

    float* out = (float*)d_out;
    const size_t ncs = (size_t)NUM_CLASSES * EMBED;

    float* loss_ptr;
    float* new_centers;
    if (out_size == (int)(ncs + 1)) {
        loss_ptr = out;
        new_centers = out + 1;
    } else {
        new_centers = out;
        loss_ptr = out + ncs;
    }

    init_kernel<<<(NUM_CLASSES + 255) / 256, 256>>>(loss_ptr);
    build_kernel<<<(BATCH_N + 255) / 256, 256>>>(y);
    fused_copy_apply_kernel<<<NUM_CLASSES / 2, 256>>>(
        reinterpret_cast<const float4*>(centers),
        reinterpret_cast<const float4*>(batch),
        new_centers, loss_ptr);
}